// round 10
// baseline (speedup 1.0000x reference)
#include <cuda_runtime.h>
#include <cuda_bf16.h>
#include <math.h>

#define B 64
#define S 4096
#define D 1024
#define NSPLIT 8
#define SPS (S / NSPLIT)   // 512
#define TILE 8
#define NTILE (SPS / TILE) // 64

#define KS 8               // split-K per operand
#define LIN_SLOTS 16       // 8 (wc@Wc) + 8 (q@Wq)

// ---------------- scratch (device globals: no allocation allowed) ----------
__device__ float g_qpart[KS * B * D];            // 2 MB  q-projection partials
__device__ float g_scores[B * S];                // 1 MB  masked raw scores
__device__ float g_pm[B * NSPLIT];
__device__ float g_pl[B * NSPLIT];
__device__ float g_pacc[B * NSPLIT * D];         // 2 MB  per-split unnormalized acc
__device__ float g_wc[B * D];
__device__ float g_linpart[LIN_SLOTS * B * D];   // 4 MB  output-GEMM partials
__device__ int   g_cnt[B];                       // flash per-batch counters

// ---------------- register-tiled skinny GEMM: partials of A @ W^T ----------
// Block: 64 b x 64 d tile over a k-chunk. 256 threads, each owns 4b x 4d.
#define GBN 64
#define GBK 32

__global__ void __launch_bounds__(256) gemm_nt(
    const float* __restrict__ A0, const float* __restrict__ W0, float* __restrict__ out0,
    const float* __restrict__ A1, const float* __restrict__ W1, float* __restrict__ out1,
    int op_shift, int kchunk)
{
    const int which = blockIdx.y >> op_shift;
    const int slot  = blockIdx.y & ((1 << op_shift) - 1);
    const float* __restrict__ A = which ? A1 : A0;
    const float* __restrict__ W = which ? W1 : W0;
    float* __restrict__ outp = (which ? out1 : out0) + (size_t)slot * B * D;
    const int k0  = slot * kchunk;
    const int dn0 = blockIdx.x * GBN;

    __shared__ float As[GBK][B];     // [k][b]
    __shared__ float Ws[GBK][GBN];   // [k][d]

    const int tid = threadIdx.x;
    const int tx = tid & 15;         // d quad
    const int ty = tid >> 4;         // b quad

    float acc[4][4] = {};

    for (int bk = 0; bk < kchunk; bk += GBK) {
        #pragma unroll
        for (int r = 0; r < 2; r++) {
            int idx  = tid + r * 256;          // 0..511
            int pair = idx & 1;
            int bb   = (idx >> 1) & 63;
            int kq   = idx >> 7;               // 0..3
            int kb   = kq * 8 + pair * 4;
            float4 v = *reinterpret_cast<const float4*>(A + (size_t)bb * D + k0 + bk + kb);
            As[kb + 0][bb] = v.x; As[kb + 1][bb] = v.y;
            As[kb + 2][bb] = v.z; As[kb + 3][bb] = v.w;
        }
        #pragma unroll
        for (int r = 0; r < 2; r++) {
            int idx  = tid + r * 256;
            int pair = idx & 1;
            int dd   = (idx >> 1) & 63;
            int kq   = idx >> 7;
            int kb   = kq * 8 + pair * 4;
            float4 v = *reinterpret_cast<const float4*>(W + (size_t)(dn0 + dd) * D + k0 + bk + kb);
            Ws[kb + 0][dd] = v.x; Ws[kb + 1][dd] = v.y;
            Ws[kb + 2][dd] = v.z; Ws[kb + 3][dd] = v.w;
        }
        __syncthreads();
        #pragma unroll
        for (int kk = 0; kk < GBK; kk++) {
            float4 a = *reinterpret_cast<const float4*>(&As[kk][ty * 4]);
            float4 w = *reinterpret_cast<const float4*>(&Ws[kk][tx * 4]);
            acc[0][0] = fmaf(a.x, w.x, acc[0][0]); acc[0][1] = fmaf(a.x, w.y, acc[0][1]);
            acc[0][2] = fmaf(a.x, w.z, acc[0][2]); acc[0][3] = fmaf(a.x, w.w, acc[0][3]);
            acc[1][0] = fmaf(a.y, w.x, acc[1][0]); acc[1][1] = fmaf(a.y, w.y, acc[1][1]);
            acc[1][2] = fmaf(a.y, w.z, acc[1][2]); acc[1][3] = fmaf(a.y, w.w, acc[1][3]);
            acc[2][0] = fmaf(a.z, w.x, acc[2][0]); acc[2][1] = fmaf(a.z, w.y, acc[2][1]);
            acc[2][2] = fmaf(a.z, w.z, acc[2][2]); acc[2][3] = fmaf(a.z, w.w, acc[2][3]);
            acc[3][0] = fmaf(a.w, w.x, acc[3][0]); acc[3][1] = fmaf(a.w, w.y, acc[3][1]);
            acc[3][2] = fmaf(a.w, w.z, acc[3][2]); acc[3][3] = fmaf(a.w, w.w, acc[3][3]);
        }
        __syncthreads();
    }
    #pragma unroll
    for (int bi = 0; bi < 4; bi++) {
        float4 r = make_float4(acc[bi][0], acc[bi][1], acc[bi][2], acc[bi][3]);
        *reinterpret_cast<float4*>(outp + (size_t)(ty * 4 + bi) * D + dn0 + tx * 4) = r;
    }
}

// ---------------- flash pass over context + fused per-batch combine --------
__global__ void __launch_bounds__(256, 4) attn_flash(
    const float* __restrict__ ctx, const int* __restrict__ mask,
    float* __restrict__ out_att, float* __restrict__ out_wc)
{
    const int split = blockIdx.x;
    const int b     = blockIdx.y;
    const int tid   = threadIdx.x;
    const int lane  = tid & 31;
    const int wid   = tid >> 5;

    __shared__ float sh_red[2][8][8];    // [parity][row][warp]
    __shared__ int   sh_last;

    // reduce q-projection split-K partials for my 4 columns
    float4 qr = make_float4(0.f, 0.f, 0.f, 0.f);
    #pragma unroll
    for (int k = 0; k < KS; k++) {
        float4 v = *reinterpret_cast<const float4*>(g_qpart + (size_t)k * B * D + b * D + tid * 4);
        qr.x += v.x; qr.y += v.y; qr.z += v.z; qr.w += v.w;
    }

    float acc0 = 0.f, acc1 = 0.f, acc2 = 0.f, acc3 = 0.f;
    float m_run = -1e30f, l_run = 0.f;

    const float* __restrict__ cbase = ctx + (size_t)b * S * D + (size_t)split * SPS * D + tid * 4;
    const int*   __restrict__ mbase = mask + b * S + split * SPS;
    const int    sgbase = b * S + split * SPS;

    const bool h16 = (lane & 16) != 0;
    const bool h8  = (lane & 8)  != 0;
    const bool h4  = (lane & 4)  != 0;
    const int  myrow = lane & 7;

    for (int t = 0; t < NTILE; t++) {
        const int s0 = t * TILE;
        const float* tb = cbase + (size_t)s0 * D;
        const int par = t & 1;

        // ---- dot pass: f transient ----
        float p[TILE];
        #pragma unroll
        for (int j = 0; j < TILE; j++) {
            float4 f = *reinterpret_cast<const float4*>(tb + (size_t)j * D);
            p[j] = fmaf(f.x, qr.x, fmaf(f.y, qr.y, fmaf(f.z, qr.z, f.w * qr.w)));
        }

        // ---- butterfly fold: 8 rows x 32 lanes -> row (lane>>2) ----
        #pragma unroll
        for (int j = 0; j < 4; j++) {
            float send = h16 ? p[j] : p[j + 4];
            float recv = __shfl_xor_sync(0xffffffffu, send, 16);
            p[j] = (h16 ? p[j + 4] : p[j]) + recv;
        }
        #pragma unroll
        for (int j = 0; j < 2; j++) {
            float send = h8 ? p[j] : p[j + 2];
            float recv = __shfl_xor_sync(0xffffffffu, send, 8);
            p[j] = (h8 ? p[j + 2] : p[j]) + recv;
        }
        float pr;
        {
            float send = h4 ? p[0] : p[1];
            float recv = __shfl_xor_sync(0xffffffffu, send, 4);
            pr = (h4 ? p[1] : p[0]) + recv;
        }
        pr += __shfl_xor_sync(0xffffffffu, pr, 2);
        pr += __shfl_xor_sync(0xffffffffu, pr, 1);
        if ((lane & 3) == 0) sh_red[par][lane >> 2][wid] = pr;

        __syncthreads();   // single barrier per tile (smem double-buffered)

        // ---- cross-warp combine (redundant per warp) + mask ----
        float v = 0.f;
        #pragma unroll
        for (int w = 0; w < 8; w++) v += sh_red[par][myrow][w];
        float a = (mbase[s0 + myrow] != 0) ? v : -1e30f;
        if (wid == 0 && lane < 8) g_scores[sgbase + s0 + lane] = a;

        float aj[TILE];
        #pragma unroll
        for (int j = 0; j < TILE; j++)
            aj[j] = __shfl_sync(0xffffffffu, a, j, 8);

        // ---- online softmax ----
        float new_m = m_run;
        #pragma unroll
        for (int j = 0; j < TILE; j++) new_m = fmaxf(new_m, aj[j]);
        float scale = __expf(m_run - new_m);
        float wj[TILE];
        float wsum = 0.f;
        #pragma unroll
        for (int j = 0; j < TILE; j++) {
            wj[j] = (aj[j] > -1e29f) ? __expf(aj[j] - new_m) : 0.f;
            wsum += wj[j];
        }
        m_run = new_m;
        l_run = fmaf(l_run, scale, wsum);
        acc0 *= scale; acc1 *= scale; acc2 *= scale; acc3 *= scale;

        // ---- weighted accumulate: re-load tile (L1 hit) ----
        #pragma unroll
        for (int j = 0; j < TILE; j++) {
            float4 f = *reinterpret_cast<const float4*>(tb + (size_t)j * D);
            acc0 = fmaf(wj[j], f.x, acc0);
            acc1 = fmaf(wj[j], f.y, acc1);
            acc2 = fmaf(wj[j], f.z, acc2);
            acc3 = fmaf(wj[j], f.w, acc3);
        }
    }

    // ---- publish split partials ----
    if (tid == 0) {
        g_pm[b * NSPLIT + split] = m_run;
        g_pl[b * NSPLIT + split] = l_run;
    }
    float* pa = g_pacc + (size_t)(b * NSPLIT + split) * D + tid * 4;
    pa[0] = acc0; pa[1] = acc1; pa[2] = acc2; pa[3] = acc3;

    // ---- last-CTA-per-batch performs the combine ----
    __threadfence();
    __syncthreads();
    if (tid == 0) {
        int prev = atomicAdd(&g_cnt[b], 1);
        sh_last = (prev == NSPLIT - 1);
    }
    __syncthreads();
    if (!sh_last) return;
    if (tid == 0) g_cnt[b] = 0;              // reset for next graph replay

    float M = -1e30f;
    #pragma unroll
    for (int i = 0; i < NSPLIT; i++) M = fmaxf(M, g_pm[b * NSPLIT + i]);
    float fac[NSPLIT];
    float L = 0.f;
    #pragma unroll
    for (int i = 0; i < NSPLIT; i++) {
        fac[i] = __expf(g_pm[b * NSPLIT + i] - M);
        L = fmaf(g_pl[b * NSPLIT + i], fac[i], L);
    }
    const float invL = 1.f / L;

    // weight_context: 1024 cols = 256 float4, one per thread
    {
        const float4* pacc4 = reinterpret_cast<const float4*>(g_pacc) + (size_t)b * NSPLIT * (D / 4) + tid;
        float4 acc = make_float4(0.f, 0.f, 0.f, 0.f);
        #pragma unroll
        for (int i = 0; i < NSPLIT; i++) {
            float4 v = pacc4[(size_t)i * (D / 4)];
            acc.x = fmaf(fac[i], v.x, acc.x);
            acc.y = fmaf(fac[i], v.y, acc.y);
            acc.z = fmaf(fac[i], v.z, acc.z);
            acc.w = fmaf(fac[i], v.w, acc.w);
        }
        float4 wc = make_float4(acc.x * invL, acc.y * invL, acc.z * invL, acc.w * invL);
        reinterpret_cast<float4*>(g_wc)[b * (D / 4) + tid] = wc;
        reinterpret_cast<float4*>(out_wc)[b * (D / 4) + tid] = wc;
    }

    // attention: 4096 scores = 1024 float4, 4 per thread
    #pragma unroll
    for (int r = 0; r < 4; r++) {
        const int s4 = r * 256 + tid;
        float4 sc = reinterpret_cast<const float4*>(g_scores)[b * (S / 4) + s4];
        float4 rr = make_float4(__expf(sc.x - M) * invL, __expf(sc.y - M) * invL,
                                __expf(sc.z - M) * invL, __expf(sc.w - M) * invL);
        reinterpret_cast<float4*>(out_att)[b * (S / 4) + s4] = rr;
    }
}

// ---------------- reduce output-GEMM partials + tanh ------------------------
// 8 threads cooperate per output float4 (2 slot-loads each), 3-level shfl_xor
// reduce; leader applies tanh + stores. 131072 threads (512 CTAs).
__global__ void __launch_bounds__(256) tanh_kernel(float* __restrict__ out) {
    const int t = blockIdx.x * blockDim.x + threadIdx.x;  // 0..131071
    const int i = t >> 3;        // float4 index 0..16383
    const int g = t & 7;         // slot subgroup

    const float4* lin4 = reinterpret_cast<const float4*>(g_linpart);
    float4 v0 = lin4[(size_t)g * (B * D / 4) + i];
    float4 v1 = lin4[(size_t)(g + 8) * (B * D / 4) + i];
    float4 s = make_float4(v0.x + v1.x, v0.y + v1.y, v0.z + v1.z, v0.w + v1.w);
    #pragma unroll
    for (int off = 1; off < 8; off <<= 1) {
        s.x += __shfl_xor_sync(0xffffffffu, s.x, off);
        s.y += __shfl_xor_sync(0xffffffffu, s.y, off);
        s.z += __shfl_xor_sync(0xffffffffu, s.z, off);
        s.w += __shfl_xor_sync(0xffffffffu, s.w, off);
    }
    if (g == 0) {
        float4 r = make_float4(tanhf(s.x), tanhf(s.y), tanhf(s.z), tanhf(s.w));
        reinterpret_cast<float4*>(out)[i] = r;
    }
}

// ---------------- launcher --------------------------------------------------
extern "C" void kernel_launch(void* const* d_in, const int* in_sizes, int n_in,
                              void* d_out, int out_size)
{
    const float* query     = (const float*)d_in[0];   // [B, D]
    const float* context   = (const float*)d_in[1];   // [B, S, D]
    const int*   ctx_mask  = (const int*)  d_in[2];   // [B, S]
    const float* W_align   = (const float*)d_in[3];   // [D, D]
    const float* W_context = (const float*)d_in[4];   // [D, D]
    const float* W_query   = (const float*)d_in[5];   // [D, D]

    float* out  = (float*)d_out;                      // [B, D]
    float* att  = out + B * D;                        // [B, S]
    float* owc  = att + B * S;                        // [B, D]

    float *pqpart = nullptr, *plinpart = nullptr, *pwc = nullptr;
    cudaGetSymbolAddress((void**)&pqpart,   g_qpart);
    cudaGetSymbolAddress((void**)&plinpart, g_linpart);
    cudaGetSymbolAddress((void**)&pwc,      g_wc);

    // 1. q partials = query @ W_align^T ONLY (gates flash; half the old work)
    gemm_nt<<<dim3(D / GBN, KS), 256>>>(query, W_align, pqpart,
                                        query, W_align, pqpart,   // unused op1
                                        3, 128);

    // 2. flash pass over context (1 GiB, read once) + fused per-batch combine
    attn_flash<<<dim3(NSPLIT, B), 256>>>(context, ctx_mask, att, owc);

    // 3. lin partials: wc @ W_context^T (slots 0-7) + query @ W_query^T (slots 8-15)
    gemm_nt<<<dim3(D / GBN, 2 * KS), 256>>>(pwc, W_context, plinpart,
                                            query, W_query, plinpart + (size_t)KS * B * D,
                                            3, 128);

    // 4. out = tanh(sum of 16 partial slots), 8-thread cooperative
    tanh_kernel<<<512, 256>>>(out);
}